// round 1
// baseline (speedup 1.0000x reference)
#include <cuda_runtime.h>
#include <math.h>

// Problem constants
#define BATCH  4
#define NTOK   1088
#define DMODEL 768
#define NHEAD  12
#define HDIM   64
#define HIDDEN 2048
#define DEPTH  4
#define TPF    272          // tokens per frame: 256 patches + 16 latents
#define MROWS  (BATCH*NTOK) // 4352

// -------- scratch (device globals: allocation-guard safe) --------
__device__ float g_H[MROWS*DMODEL];
__device__ float g_Q[MROWS*DMODEL];
__device__ float g_K[MROWS*DMODEL];
__device__ float g_V[MROWS*DMODEL];
__device__ float g_O[MROWS*DMODEL];
__device__ float g_G[MROWS*HIDDEN];
__device__ float g_COS[256*HDIM];
__device__ float g_SIN[256*HDIM];

// ---------------- RoPE tables ----------------
// freqs: first 32 dims use gy (idx/16), last 32 use gx (idx%16);
// within each half, freq pair p repeated twice: inv_freq[p] = 10000^(-p/16)
__global__ void rope_init_kernel() {
    int i = blockIdx.x;     // grid index 0..255
    int d = threadIdx.x;    // 0..63
    int gy = i >> 4, gx = i & 15;
    float pos  = (d < 32) ? (float)gy : (float)gx;
    int   p    = (d & 31) >> 1;
    float freq = powf(10000.f, -(float)p / 16.f);
    float ang  = pos * freq;
    g_COS[i*HDIM + d] = cosf(ang);
    g_SIN[i*HDIM + d] = sinf(ang);
}

// ---------------- RMSNorm over D=768 ----------------
__global__ void rmsnorm_kernel(const float* __restrict__ x,
                               const float* __restrict__ w,
                               float* __restrict__ out) {
    int row = blockIdx.x;
    int tid = threadIdx.x;  // 192 threads, each a float4 (192*4 = 768)
    const float4* xr = (const float4*)(x + (size_t)row*DMODEL);
    float4 v = xr[tid];
    float ss = v.x*v.x + v.y*v.y + v.z*v.z + v.w*v.w;
#pragma unroll
    for (int o = 16; o > 0; o >>= 1) ss += __shfl_xor_sync(0xffffffffu, ss, o);
    __shared__ float red[6];
    __shared__ float rtot;
    int wid = tid >> 5, lane = tid & 31;
    if (lane == 0) red[wid] = ss;
    __syncthreads();
    if (tid == 0) {
        float t = 0.f;
#pragma unroll
        for (int i = 0; i < 6; i++) t += red[i];
        rtot = rsqrtf(t / 768.f + 1e-6f);
    }
    __syncthreads();
    float r = rtot;
    float4 wv = ((const float4*)w)[tid];
    float4 ov = make_float4(v.x*r*wv.x, v.y*r*wv.y, v.z*r*wv.z, v.w*r*wv.w);
    ((float4*)(out + (size_t)row*DMODEL))[tid] = ov;
}

// ---------------- RoPE2D + QKNorm (per (row, head)) ----------------
// grid: (MROWS, 3), block 128 = 4 warps, one warp per head
__global__ void rope_qknorm_kernel(float* __restrict__ q, const float* __restrict__ w) {
    int m    = blockIdx.x;
    int n    = m % NTOK;
    int head = blockIdx.y*4 + (threadIdx.x >> 5);
    int lane = threadIdx.x & 31;
    float* row = q + (size_t)m*DMODEL + head*HDIM;
    float2 v = ((float2*)row)[lane];
    int pos = n % TPF;
    if (pos < 256) {  // patch token -> apply rope (grid index == pos)
        float c = g_COS[pos*HDIM + lane*2];
        float s = g_SIN[pos*HDIM + lane*2];
        float nv0 = v.x*c - v.y*s;
        float nv1 = v.y*c + v.x*s;
        v.x = nv0; v.y = nv1;
    }
    float ss = v.x*v.x + v.y*v.y;
#pragma unroll
    for (int o = 16; o > 0; o >>= 1) ss += __shfl_xor_sync(0xffffffffu, ss, o);
    float r = rsqrtf(ss / 64.f + 1e-6f);
    float2 wv = ((const float2*)w)[lane];
    v.x *= r*wv.x; v.y *= r*wv.y;
    ((float2*)row)[lane] = v;
}

// ---------------- SGEMM 128x128x8, fp32, fused epilogues ----------------
// EPI 0: C = A@B ; EPI 1: C += A@B ; EPI 2: C = silu(A@B) * R
template<int EPI>
__global__ void __launch_bounds__(256)
sgemm_kernel(const float* __restrict__ A, const float* __restrict__ B,
             float* C, const float* R, int M, int N, int K) {
    __shared__ float As[8][128];
    __shared__ float Bs[8][128];
    int bm = blockIdx.y * 128, bn = blockIdx.x * 128;
    int tid = threadIdx.x;
    int tx = tid & 15, ty = tid >> 4;
    float acc[8][8];
#pragma unroll
    for (int i = 0; i < 8; i++)
#pragma unroll
        for (int j = 0; j < 8; j++) acc[i][j] = 0.f;

    int arow = tid >> 1;
    int acol = (tid & 1) * 4;
    int brow = tid >> 5;
    int bcol = (tid & 31) * 4;
    const float* Aptr = A + (size_t)(bm + arow)*K + acol;
    const float* Bptr = B + (size_t)brow*N + bn + bcol;

    for (int k0 = 0; k0 < K; k0 += 8) {
        float4 a4 = *(const float4*)Aptr;
        float4 b4 = *(const float4*)Bptr;
        As[acol+0][arow] = a4.x; As[acol+1][arow] = a4.y;
        As[acol+2][arow] = a4.z; As[acol+3][arow] = a4.w;
        *(float4*)&Bs[brow][bcol] = b4;
        __syncthreads();
#pragma unroll
        for (int kk = 0; kk < 8; kk++) {
            float af[8], bf[8];
            *(float4*)&af[0] = *(const float4*)&As[kk][ty*8];
            *(float4*)&af[4] = *(const float4*)&As[kk][ty*8+4];
            *(float4*)&bf[0] = *(const float4*)&Bs[kk][tx*8];
            *(float4*)&bf[4] = *(const float4*)&Bs[kk][tx*8+4];
#pragma unroll
            for (int i = 0; i < 8; i++)
#pragma unroll
                for (int j = 0; j < 8; j++) acc[i][j] += af[i]*bf[j];
        }
        __syncthreads();
        Aptr += 8;
        Bptr += (size_t)8*N;
    }

    int row0 = bm + ty*8;
    int col0 = bn + tx*8;
#pragma unroll
    for (int i = 0; i < 8; i++) {
        float*       crow = C + (size_t)(row0+i)*N + col0;
        const float* rrow = R + (size_t)(row0+i)*N + col0;
#pragma unroll
        for (int j = 0; j < 8; j++) {
            float v = acc[i][j];
            if (EPI == 1) v += crow[j];
            else if (EPI == 2) {
                float z = v;
                v = (z / (1.f + expf(-z))) * rrow[j];
            }
            crow[j] = v;
        }
    }
}

// ---------------- Attention (mask-structure-aware flash) ----------------
// grid: (20, NHEAD, BATCH); 20 tiles per frame-group:
//   sub 0..3 -> 64 patch queries, keys = 256 same-frame patches (no mask needed)
//   sub 4    -> 16 latent queries, keys = [0, (frame+1)*272) (no mask needed)
__global__ void __launch_bounds__(64)
attn_kernel(const float* __restrict__ Q, const float* __restrict__ Kp,
            const float* __restrict__ Vp, float* __restrict__ Op) {
    int b = blockIdx.z, h = blockIdx.y;
    int frame = blockIdx.x / 5, sub = blockIdx.x % 5;
    int q0, nq, k0, kend;
    if (sub < 4) { q0 = frame*TPF + sub*64; nq = 64; k0 = frame*TPF; kend = k0 + 256; }
    else         { q0 = frame*TPF + 256;    nq = 16; k0 = 0;         kend = (frame+1)*TPF; }
    int tq = threadIdx.x;

    __shared__ float Qs[64][68];
    __shared__ float Ks[32][68];
    __shared__ float Vs[32][68];

    size_t bbase = (size_t)b*NTOK*DMODEL + h*HDIM;

    for (int it = 0; it < nq; it++)
        Qs[it][tq] = Q[bbase + (size_t)(q0+it)*DMODEL + tq];
    __syncthreads();

    float mrun = -1e30f, lrun = 0.f;
    float Oa[64];
#pragma unroll
    for (int d = 0; d < 64; d++) Oa[d] = 0.f;

    for (int kt = k0; kt < kend; kt += 32) {
        int kn = kend - kt; if (kn > 32) kn = 32;
#pragma unroll
        for (int r = 0; r < 32; r++) {
            float kv = 0.f, vv = 0.f;
            if (r < kn) {
                kv = Kp[bbase + (size_t)(kt+r)*DMODEL + tq];
                vv = Vp[bbase + (size_t)(kt+r)*DMODEL + tq];
            }
            Ks[r][tq] = kv;
            Vs[r][tq] = vv;
        }
        __syncthreads();

        if (tq < nq) {
            float s[32];
#pragma unroll
            for (int j = 0; j < 32; j++) s[j] = 0.f;
#pragma unroll
            for (int d4 = 0; d4 < 16; d4++) {
                float4 q4 = *(const float4*)&Qs[tq][d4*4];
#pragma unroll
                for (int j = 0; j < 32; j++) {
                    float4 k4 = *(const float4*)&Ks[j][d4*4];
                    s[j] += q4.x*k4.x + q4.y*k4.y + q4.z*k4.z + q4.w*k4.w;
                }
            }
            // scale -> softcap -> (range mask) -> online softmax
            float mx = -1e30f;
#pragma unroll
            for (int j = 0; j < 32; j++) {
                float sv = 50.f * tanhf(s[j] * (0.125f/50.f));
                s[j] = (kt + j < kend) ? sv : -1e30f;
                mx = fmaxf(mx, s[j]);
            }
            float mnew = fmaxf(mrun, mx);
            float corr = __expf(mrun - mnew);
            lrun *= corr;
#pragma unroll
            for (int d = 0; d < 64; d++) Oa[d] *= corr;
#pragma unroll
            for (int j = 0; j < 32; j++) {
                float p = __expf(s[j] - mnew);
                lrun += p;
#pragma unroll
                for (int d4 = 0; d4 < 16; d4++) {
                    float4 v4 = *(const float4*)&Vs[j][d4*4];
                    Oa[d4*4+0] += p*v4.x; Oa[d4*4+1] += p*v4.y;
                    Oa[d4*4+2] += p*v4.z; Oa[d4*4+3] += p*v4.w;
                }
            }
            mrun = mnew;
        }
        __syncthreads();
    }

    if (tq < nq) {
        float inv = 1.f / lrun;
        float* orow = Op + bbase + (size_t)(q0+tq)*DMODEL;
#pragma unroll
        for (int d = 0; d < 64; d++) orow[d] = Oa[d]*inv;
    }
}

// ---------------- launch ----------------
extern "C" void kernel_launch(void* const* d_in, const int* in_sizes, int n_in,
                              void* d_out, int out_size) {
    const float* x   = (const float*)d_in[0];
    const float* wq  = (const float*)d_in[1];
    const float* wk  = (const float*)d_in[2];
    const float* wv  = (const float*)d_in[3];
    const float* wo  = (const float*)d_in[4];
    const float* qnw = (const float*)d_in[5];
    const float* knw = (const float*)d_in[6];
    const float* n1w = (const float*)d_in[7];
    const float* n2w = (const float*)d_in[8];
    const float* w1  = (const float*)d_in[9];
    const float* w2  = (const float*)d_in[10];
    const float* w3  = (const float*)d_in[11];
    // d_in[12] mask, d_in[13] rope_indices: structure is computed analytically

    float* xbuf = (float*)d_out;   // residual stream lives in the output buffer

    float *H, *Q, *K, *V, *O, *G;
    cudaGetSymbolAddress((void**)&H, g_H);
    cudaGetSymbolAddress((void**)&Q, g_Q);
    cudaGetSymbolAddress((void**)&K, g_K);
    cudaGetSymbolAddress((void**)&V, g_V);
    cudaGetSymbolAddress((void**)&O, g_O);
    cudaGetSymbolAddress((void**)&G, g_G);

    cudaMemcpyAsync(xbuf, x, sizeof(float)*(size_t)MROWS*DMODEL, cudaMemcpyDeviceToDevice);
    rope_init_kernel<<<256, 64>>>();

    dim3 gD(DMODEL/128, MROWS/128);   // (6, 34)
    dim3 gF(HIDDEN/128, MROWS/128);   // (16, 34)
    dim3 gR(MROWS, 3);
    dim3 gA(20, NHEAD, BATCH);

    for (int l = 0; l < DEPTH; l++) {
        const float* wq_l = wq + (size_t)l*DMODEL*DMODEL;
        const float* wk_l = wk + (size_t)l*DMODEL*DMODEL;
        const float* wv_l = wv + (size_t)l*DMODEL*DMODEL;
        const float* wo_l = wo + (size_t)l*DMODEL*DMODEL;
        const float* w1_l = w1 + (size_t)l*DMODEL*HIDDEN;
        const float* w3_l = w3 + (size_t)l*DMODEL*HIDDEN;
        const float* w2_l = w2 + (size_t)l*HIDDEN*DMODEL;

        // --- attention block ---
        rmsnorm_kernel<<<MROWS, 192>>>(xbuf, n1w + l*DMODEL, H);
        sgemm_kernel<0><<<gD, 256>>>(H, wq_l, Q, Q, MROWS, DMODEL, DMODEL);
        sgemm_kernel<0><<<gD, 256>>>(H, wk_l, K, K, MROWS, DMODEL, DMODEL);
        sgemm_kernel<0><<<gD, 256>>>(H, wv_l, V, V, MROWS, DMODEL, DMODEL);
        rope_qknorm_kernel<<<gR, 128>>>(Q, qnw + l*HDIM);
        rope_qknorm_kernel<<<gR, 128>>>(K, knw + l*HDIM);
        attn_kernel<<<gA, 64>>>(Q, K, V, O);
        sgemm_kernel<1><<<gD, 256>>>(O, wo_l, xbuf, xbuf, MROWS, DMODEL, DMODEL);

        // --- MLP block (SwiGLU) ---
        rmsnorm_kernel<<<MROWS, 192>>>(xbuf, n2w + l*DMODEL, H);
        sgemm_kernel<0><<<gF, 256>>>(H, w3_l, G, G, MROWS, HIDDEN, DMODEL);   // G = h@w3
        sgemm_kernel<2><<<gF, 256>>>(H, w1_l, G, G, MROWS, HIDDEN, DMODEL);   // G = silu(h@w1)*G
        sgemm_kernel<1><<<gD, 256>>>(G, w2_l, xbuf, xbuf, MROWS, DMODEL, HIDDEN);
    }
}

// round 2
// speedup vs baseline: 1.2532x; 1.2532x over previous
#include <cuda_runtime.h>
#include <math.h>
#include <mma.h>

using namespace nvcuda;

// Problem constants
#define BATCH  4
#define NTOK   1088
#define DMODEL 768
#define NHEAD  12
#define HDIM   64
#define HIDDEN 2048
#define DEPTH  4
#define TPF    272          // tokens per frame: 256 patches + 16 latents
#define MROWS  (BATCH*NTOK) // 4352

// -------- scratch (device globals: allocation-guard safe) --------
__device__ float g_H[MROWS*DMODEL];
__device__ float g_Q[MROWS*DMODEL];
__device__ float g_K[MROWS*DMODEL];
__device__ float g_V[MROWS*DMODEL];
__device__ float g_O[MROWS*DMODEL];
__device__ float g_G[MROWS*HIDDEN];
__device__ float g_COS[256*HDIM];
__device__ float g_SIN[256*HDIM];

// ---------------- RoPE tables ----------------
__global__ void rope_init_kernel() {
    int i = blockIdx.x;     // grid index 0..255
    int d = threadIdx.x;    // 0..63
    int gy = i >> 4, gx = i & 15;
    float pos  = (d < 32) ? (float)gy : (float)gx;
    int   p    = (d & 31) >> 1;
    float freq = powf(10000.f, -(float)p / 16.f);
    float ang  = pos * freq;
    g_COS[i*HDIM + d] = cosf(ang);
    g_SIN[i*HDIM + d] = sinf(ang);
}

// ---------------- RMSNorm over D=768 ----------------
__global__ void rmsnorm_kernel(const float* __restrict__ x,
                               const float* __restrict__ w,
                               float* __restrict__ out) {
    int row = blockIdx.x;
    int tid = threadIdx.x;  // 192 threads, each a float4
    const float4* xr = (const float4*)(x + (size_t)row*DMODEL);
    float4 v = xr[tid];
    float ss = v.x*v.x + v.y*v.y + v.z*v.z + v.w*v.w;
#pragma unroll
    for (int o = 16; o > 0; o >>= 1) ss += __shfl_xor_sync(0xffffffffu, ss, o);
    __shared__ float red[6];
    __shared__ float rtot;
    int wid = tid >> 5, lane = tid & 31;
    if (lane == 0) red[wid] = ss;
    __syncthreads();
    if (tid == 0) {
        float t = 0.f;
#pragma unroll
        for (int i = 0; i < 6; i++) t += red[i];
        rtot = rsqrtf(t / 768.f + 1e-6f);
    }
    __syncthreads();
    float r = rtot;
    float4 wv = ((const float4*)w)[tid];
    float4 ov = make_float4(v.x*r*wv.x, v.y*r*wv.y, v.z*r*wv.z, v.w*r*wv.w);
    ((float4*)(out + (size_t)row*DMODEL))[tid] = ov;
}

// ---------------- RoPE2D + QKNorm (per (row, head)) ----------------
__global__ void rope_qknorm_kernel(float* __restrict__ q, const float* __restrict__ w) {
    int m    = blockIdx.x;
    int n    = m % NTOK;
    int head = blockIdx.y*4 + (threadIdx.x >> 5);
    int lane = threadIdx.x & 31;
    float* row = q + (size_t)m*DMODEL + head*HDIM;
    float2 v = ((float2*)row)[lane];
    int pos = n % TPF;
    if (pos < 256) {  // patch token -> apply rope (grid index == pos)
        float c = g_COS[pos*HDIM + lane*2];
        float s = g_SIN[pos*HDIM + lane*2];
        float nv0 = v.x*c - v.y*s;
        float nv1 = v.y*c + v.x*s;
        v.x = nv0; v.y = nv1;
    }
    float ss = v.x*v.x + v.y*v.y;
#pragma unroll
    for (int o = 16; o > 0; o >>= 1) ss += __shfl_xor_sync(0xffffffffu, ss, o);
    float r = rsqrtf(ss / 64.f + 1e-6f);
    float2 wv = ((const float2*)w)[lane];
    v.x *= r*wv.x; v.y *= r*wv.y;
    ((float2*)row)[lane] = v;
}

// ---------------- TF32 tensor-core GEMM, 128x64 tile, fused epilogues ----------------
// EPI 0: C = A@B ; EPI 1: C += A@B ; EPI 2: C = silu(A@B) * R
// Block: 256 threads = 8 warps arranged 4(m) x 2(n), each warp 32x32.
// Smem: double-buffered stages [A 128x16 | B 16x64] = 3072 floats/stage;
// epilogue reuses the same 8192-float buffer (1024 floats per warp).
template<int EPI>
__global__ void __launch_bounds__(256)
tgemm_kernel(const float* __restrict__ A, const float* __restrict__ B,
             float* C, const float* R, int M, int N, int K) {
    __shared__ float sm[8192];

    int tid  = threadIdx.x;
    int wid  = tid >> 5;
    int lane = tid & 31;
    int wm = wid & 3;        // 0..3  (rows 32*wm)
    int wn = wid >> 2;       // 0..1  (cols 32*wn)
    int bm = blockIdx.y * 128, bn = blockIdx.x * 64;

    wmma::fragment<wmma::accumulator, 16, 16, 8, float> acc[2][2];
#pragma unroll
    for (int i = 0; i < 2; i++)
#pragma unroll
        for (int j = 0; j < 2; j++) wmma::fill_fragment(acc[i][j], 0.f);

    // ---- stage loader: global fp32 -> smem tf32 ----
    auto load_stage = [&](int buf, int k0) {
        float* As = sm + buf*3072;
        float* Bs = sm + buf*3072 + 2048;
        // A tile 128x16: 512 float4, 2 per thread
#pragma unroll
        for (int i = 0; i < 2; i++) {
            int f = tid + i*256;
            int r = f >> 2;
            int c = (f & 3) * 4;
            float4 v = *(const float4*)&A[(size_t)(bm + r)*K + k0 + c];
            float* dst = As + r*16 + c;
            dst[0] = wmma::__float_to_tf32(v.x);
            dst[1] = wmma::__float_to_tf32(v.y);
            dst[2] = wmma::__float_to_tf32(v.z);
            dst[3] = wmma::__float_to_tf32(v.w);
        }
        // B tile 16x64: 256 float4, 1 per thread
        {
            int r = tid >> 4;
            int c = (tid & 15) * 4;
            float4 v = *(const float4*)&B[(size_t)(k0 + r)*N + bn + c];
            float* dst = Bs + r*64 + c;
            dst[0] = wmma::__float_to_tf32(v.x);
            dst[1] = wmma::__float_to_tf32(v.y);
            dst[2] = wmma::__float_to_tf32(v.z);
            dst[3] = wmma::__float_to_tf32(v.w);
        }
    };

    load_stage(0, 0);
    __syncthreads();

    int nstages = K / 16;
    for (int s = 0; s < nstages; s++) {
        int cur = s & 1;
        if (s + 1 < nstages) load_stage(cur ^ 1, (s + 1) * 16);

        const float* As = sm + cur*3072;
        const float* Bs = sm + cur*3072 + 2048;
#pragma unroll
        for (int kk = 0; kk < 16; kk += 8) {
            wmma::fragment<wmma::matrix_a, 16, 16, 8, wmma::precision::tf32, wmma::row_major> a[2];
            wmma::fragment<wmma::matrix_b, 16, 16, 8, wmma::precision::tf32, wmma::row_major> b[2];
#pragma unroll
            for (int i = 0; i < 2; i++)
                wmma::load_matrix_sync(a[i], As + (wm*32 + i*16)*16 + kk, 16);
#pragma unroll
            for (int j = 0; j < 2; j++)
                wmma::load_matrix_sync(b[j], Bs + kk*64 + wn*32 + j*16, 64);
#pragma unroll
            for (int i = 0; i < 2; i++)
#pragma unroll
                for (int j = 0; j < 2; j++)
                    wmma::mma_sync(acc[i][j], a[i], b[j], acc[i][j]);
        }
        __syncthreads();
    }

    // ---- epilogue: acc -> smem -> global with fused op ----
    float* epi = sm + wid*1024;   // 32x32 per-warp region
#pragma unroll
    for (int i = 0; i < 2; i++)
#pragma unroll
        for (int j = 0; j < 2; j++)
            wmma::store_matrix_sync(epi + i*16*32 + j*16, acc[i][j], 32, wmma::mem_row_major);
    __syncwarp();

    int row = bm + wm*32 + lane;
    float*       crow = C + (size_t)row*N + bn + wn*32;
    const float* rrow = R + (size_t)row*N + bn + wn*32;
    const float* erow = epi + lane*32;
#pragma unroll
    for (int j4 = 0; j4 < 8; j4++) {
        float4 v = ((const float4*)erow)[j4];
        if (EPI == 1) {
            float4 c = ((const float4*)crow)[j4];
            v.x += c.x; v.y += c.y; v.z += c.z; v.w += c.w;
        } else if (EPI == 2) {
            float4 rv = ((const float4*)rrow)[j4];
            v.x = (v.x / (1.f + expf(-v.x))) * rv.x;
            v.y = (v.y / (1.f + expf(-v.y))) * rv.y;
            v.z = (v.z / (1.f + expf(-v.z))) * rv.z;
            v.w = (v.w / (1.f + expf(-v.w))) * rv.w;
        }
        ((float4*)crow)[j4] = v;
    }
}

// ---------------- Attention (mask-structure-aware flash) ----------------
__global__ void __launch_bounds__(64)
attn_kernel(const float* __restrict__ Q, const float* __restrict__ Kp,
            const float* __restrict__ Vp, float* __restrict__ Op) {
    int b = blockIdx.z, h = blockIdx.y;
    int frame = blockIdx.x / 5, sub = blockIdx.x % 5;
    int q0, nq, k0, kend;
    if (sub < 4) { q0 = frame*TPF + sub*64; nq = 64; k0 = frame*TPF; kend = k0 + 256; }
    else         { q0 = frame*TPF + 256;    nq = 16; k0 = 0;         kend = (frame+1)*TPF; }
    int tq = threadIdx.x;

    __shared__ float Qs[64][68];
    __shared__ float Ks[32][68];
    __shared__ float Vs[32][68];

    size_t bbase = (size_t)b*NTOK*DMODEL + h*HDIM;

    for (int it = 0; it < nq; it++)
        Qs[it][tq] = Q[bbase + (size_t)(q0+it)*DMODEL + tq];
    __syncthreads();

    float mrun = -1e30f, lrun = 0.f;
    float Oa[64];
#pragma unroll
    for (int d = 0; d < 64; d++) Oa[d] = 0.f;

    for (int kt = k0; kt < kend; kt += 32) {
        int kn = kend - kt; if (kn > 32) kn = 32;
#pragma unroll
        for (int r = 0; r < 32; r++) {
            float kv = 0.f, vv = 0.f;
            if (r < kn) {
                kv = Kp[bbase + (size_t)(kt+r)*DMODEL + tq];
                vv = Vp[bbase + (size_t)(kt+r)*DMODEL + tq];
            }
            Ks[r][tq] = kv;
            Vs[r][tq] = vv;
        }
        __syncthreads();

        if (tq < nq) {
            float s[32];
#pragma unroll
            for (int j = 0; j < 32; j++) s[j] = 0.f;
#pragma unroll
            for (int d4 = 0; d4 < 16; d4++) {
                float4 q4 = *(const float4*)&Qs[tq][d4*4];
#pragma unroll
                for (int j = 0; j < 32; j++) {
                    float4 k4 = *(const float4*)&Ks[j][d4*4];
                    s[j] += q4.x*k4.x + q4.y*k4.y + q4.z*k4.z + q4.w*k4.w;
                }
            }
            float mx = -1e30f;
#pragma unroll
            for (int j = 0; j < 32; j++) {
                float sv = 50.f * tanhf(s[j] * (0.125f/50.f));
                s[j] = (kt + j < kend) ? sv : -1e30f;
                mx = fmaxf(mx, s[j]);
            }
            float mnew = fmaxf(mrun, mx);
            float corr = __expf(mrun - mnew);
            lrun *= corr;
#pragma unroll
            for (int d = 0; d < 64; d++) Oa[d] *= corr;
#pragma unroll
            for (int j = 0; j < 32; j++) {
                float p = __expf(s[j] - mnew);
                lrun += p;
#pragma unroll
                for (int d4 = 0; d4 < 16; d4++) {
                    float4 v4 = *(const float4*)&Vs[j][d4*4];
                    Oa[d4*4+0] += p*v4.x; Oa[d4*4+1] += p*v4.y;
                    Oa[d4*4+2] += p*v4.z; Oa[d4*4+3] += p*v4.w;
                }
            }
            mrun = mnew;
        }
        __syncthreads();
    }

    if (tq < nq) {
        float inv = 1.f / lrun;
        float* orow = Op + bbase + (size_t)(q0+tq)*DMODEL;
#pragma unroll
        for (int d = 0; d < 64; d++) orow[d] = Oa[d]*inv;
    }
}

// ---------------- launch ----------------
extern "C" void kernel_launch(void* const* d_in, const int* in_sizes, int n_in,
                              void* d_out, int out_size) {
    const float* x   = (const float*)d_in[0];
    const float* wq  = (const float*)d_in[1];
    const float* wk  = (const float*)d_in[2];
    const float* wv  = (const float*)d_in[3];
    const float* wo  = (const float*)d_in[4];
    const float* qnw = (const float*)d_in[5];
    const float* knw = (const float*)d_in[6];
    const float* n1w = (const float*)d_in[7];
    const float* n2w = (const float*)d_in[8];
    const float* w1  = (const float*)d_in[9];
    const float* w2  = (const float*)d_in[10];
    const float* w3  = (const float*)d_in[11];

    float* xbuf = (float*)d_out;   // residual stream lives in the output buffer

    float *H, *Q, *K, *V, *O, *G;
    cudaGetSymbolAddress((void**)&H, g_H);
    cudaGetSymbolAddress((void**)&Q, g_Q);
    cudaGetSymbolAddress((void**)&K, g_K);
    cudaGetSymbolAddress((void**)&V, g_V);
    cudaGetSymbolAddress((void**)&O, g_O);
    cudaGetSymbolAddress((void**)&G, g_G);

    cudaMemcpyAsync(xbuf, x, sizeof(float)*(size_t)MROWS*DMODEL, cudaMemcpyDeviceToDevice);
    rope_init_kernel<<<256, 64>>>();

    dim3 gD(DMODEL/64, MROWS/128);   // (12, 34)
    dim3 gF(HIDDEN/64, MROWS/128);   // (32, 34)
    dim3 gR(MROWS, 3);
    dim3 gA(20, NHEAD, BATCH);

    for (int l = 0; l < DEPTH; l++) {
        const float* wq_l = wq + (size_t)l*DMODEL*DMODEL;
        const float* wk_l = wk + (size_t)l*DMODEL*DMODEL;
        const float* wv_l = wv + (size_t)l*DMODEL*DMODEL;
        const float* wo_l = wo + (size_t)l*DMODEL*DMODEL;
        const float* w1_l = w1 + (size_t)l*DMODEL*HIDDEN;
        const float* w3_l = w3 + (size_t)l*DMODEL*HIDDEN;
        const float* w2_l = w2 + (size_t)l*HIDDEN*DMODEL;

        // --- attention block ---
        rmsnorm_kernel<<<MROWS, 192>>>(xbuf, n1w + l*DMODEL, H);
        tgemm_kernel<0><<<gD, 256>>>(H, wq_l, Q, Q, MROWS, DMODEL, DMODEL);
        tgemm_kernel<0><<<gD, 256>>>(H, wk_l, K, K, MROWS, DMODEL, DMODEL);
        tgemm_kernel<0><<<gD, 256>>>(H, wv_l, V, V, MROWS, DMODEL, DMODEL);
        rope_qknorm_kernel<<<gR, 128>>>(Q, qnw + l*HDIM);
        rope_qknorm_kernel<<<gR, 128>>>(K, knw + l*HDIM);
        attn_kernel<<<gA, 64>>>(Q, K, V, O);
        tgemm_kernel<1><<<gD, 256>>>(O, wo_l, xbuf, xbuf, MROWS, DMODEL, DMODEL);

        // --- MLP block (SwiGLU) ---
        rmsnorm_kernel<<<MROWS, 192>>>(xbuf, n2w + l*DMODEL, H);
        tgemm_kernel<0><<<gF, 256>>>(H, w3_l, G, G, MROWS, HIDDEN, DMODEL);   // G = h@w3
        tgemm_kernel<2><<<gF, 256>>>(H, w1_l, G, G, MROWS, HIDDEN, DMODEL);   // G = silu(h@w1)*G
        tgemm_kernel<1><<<gD, 256>>>(G, w2_l, xbuf, xbuf, MROWS, DMODEL, HIDDEN);
    }
}

// round 4
// speedup vs baseline: 1.4196x; 1.1328x over previous
#include <cuda_runtime.h>
#include <math.h>
#include <mma.h>

using namespace nvcuda;

// Problem constants
#define BATCH  4
#define NTOK   1088
#define DMODEL 768
#define NHEAD  12
#define HDIM   64
#define HIDDEN 2048
#define DEPTH  4
#define TPF    272          // tokens per frame: 256 patches + 16 latents
#define MROWS  (BATCH*NTOK) // 4352

// -------- scratch (device globals: allocation-guard safe; 256B-aligned for cp.async) --------
__device__ __align__(256) float g_H[MROWS*DMODEL];
__device__ __align__(256) float g_Q[MROWS*DMODEL];
__device__ __align__(256) float g_K[MROWS*DMODEL];
__device__ __align__(256) float g_V[MROWS*DMODEL];
__device__ __align__(256) float g_O[MROWS*DMODEL];
__device__ __align__(256) float g_G[MROWS*HIDDEN];
__device__ __align__(256) float g_COS[256*HDIM];
__device__ __align__(256) float g_SIN[256*HDIM];

// ---------------- cp.async helpers ----------------
__device__ __forceinline__ void cp_async16(void* smem_dst, const void* gmem_src) {
    unsigned s = (unsigned)__cvta_generic_to_shared(smem_dst);
    asm volatile("cp.async.cg.shared.global [%0], [%1], 16;\n" :: "r"(s), "l"(gmem_src));
}
__device__ __forceinline__ void cp_commit() {
    asm volatile("cp.async.commit_group;\n" ::: "memory");
}
template<int N>
__device__ __forceinline__ void cp_wait() {
    asm volatile("cp.async.wait_group %0;\n" :: "n"(N) : "memory");
}

// ---------------- RoPE tables ----------------
__global__ void rope_init_kernel() {
    int i = blockIdx.x;     // grid index 0..255
    int d = threadIdx.x;    // 0..63
    int gy = i >> 4, gx = i & 15;
    float pos  = (d < 32) ? (float)gy : (float)gx;
    int   p    = (d & 31) >> 1;
    float freq = powf(10000.f, -(float)p / 16.f);
    float ang  = pos * freq;
    g_COS[i*HDIM + d] = cosf(ang);
    g_SIN[i*HDIM + d] = sinf(ang);
}

// ---------------- RMSNorm over D=768 ----------------
__global__ void rmsnorm_kernel(const float* __restrict__ x,
                               const float* __restrict__ w,
                               float* __restrict__ out) {
    int row = blockIdx.x;
    int tid = threadIdx.x;  // 192 threads, each a float4
    const float4* xr = (const float4*)(x + (size_t)row*DMODEL);
    float4 v = xr[tid];
    float ss = v.x*v.x + v.y*v.y + v.z*v.z + v.w*v.w;
#pragma unroll
    for (int o = 16; o > 0; o >>= 1) ss += __shfl_xor_sync(0xffffffffu, ss, o);
    __shared__ float red[6];
    __shared__ float rtot;
    int wid = tid >> 5, lane = tid & 31;
    if (lane == 0) red[wid] = ss;
    __syncthreads();
    if (tid == 0) {
        float t = 0.f;
#pragma unroll
        for (int i = 0; i < 6; i++) t += red[i];
        rtot = rsqrtf(t / 768.f + 1e-6f);
    }
    __syncthreads();
    float r = rtot;
    float4 wv = ((const float4*)w)[tid];
    float4 ov = make_float4(v.x*r*wv.x, v.y*r*wv.y, v.z*r*wv.z, v.w*r*wv.w);
    ((float4*)(out + (size_t)row*DMODEL))[tid] = ov;
}

// ---------------- RoPE2D + QKNorm (per (row, head)) ----------------
__global__ void rope_qknorm_kernel(float* __restrict__ q, const float* __restrict__ w) {
    int m    = blockIdx.x;
    int n    = m % NTOK;
    int head = blockIdx.y*4 + (threadIdx.x >> 5);
    int lane = threadIdx.x & 31;
    float* row = q + (size_t)m*DMODEL + head*HDIM;
    float2 v = ((float2*)row)[lane];
    int pos = n % TPF;
    if (pos < 256) {  // patch token -> apply rope (grid index == pos)
        float c = g_COS[pos*HDIM + lane*2];
        float s = g_SIN[pos*HDIM + lane*2];
        float nv0 = v.x*c - v.y*s;
        float nv1 = v.y*c + v.x*s;
        v.x = nv0; v.y = nv1;
    }
    float ss = v.x*v.x + v.y*v.y;
#pragma unroll
    for (int o = 16; o > 0; o >>= 1) ss += __shfl_xor_sync(0xffffffffu, ss, o);
    float r = rsqrtf(ss / 64.f + 1e-6f);
    float2 wv = ((const float2*)w)[lane];
    v.x *= r*wv.x; v.y *= r*wv.y;
    ((float2*)row)[lane] = v;
}

// ---------------- TF32 tensor-core GEMM, 128x128x16, cp.async double-buffer ----------------
// EPI 0: C = A@B ; EPI 1: C += A@B ; EPI 2: C = silu(A@B) * R
// 256 threads = 8 warps (2 m-rows x 4 n-cols), each warp owns 64x32 (4x2 wmma frags).
// A tile 128x16 padded stride 20; B tile 16x128 padded stride 132.
#define ASTR 20
#define BSTR 132

template<int EPI>
__global__ void __launch_bounds__(256)
tgemm_kernel(const float* __restrict__ A, const float* __restrict__ B,
             float* C, const float* R, int M, int N, int K) {
    __shared__ __align__(32) float As[2][128*ASTR];
    __shared__ __align__(32) float Bs[2][16*BSTR];

    int tid  = threadIdx.x;
    int wid  = tid >> 5;
    int wm = wid >> 2;       // 0..1 (row block of 64)
    int wn = wid & 3;        // 0..3 (col block of 32)
    int bm = blockIdx.y * 128, bn = blockIdx.x * 128;

    wmma::fragment<wmma::accumulator, 16, 16, 8, float> acc[4][2];
#pragma unroll
    for (int i = 0; i < 4; i++)
#pragma unroll
        for (int j = 0; j < 2; j++) wmma::fill_fragment(acc[i][j], 0.f);

    // A: 128x16 = 512 float4 chunks (2/thread); B: 16x128 = 512 chunks (2/thread)
    int ar0 = tid >> 2, ac0 = (tid & 3) * 4;           // rows tid/4, tid/4+64
    int br0 = tid >> 5, bc0 = (tid & 31) * 4;          // rows tid/32, +8

    auto load_stage = [&](int buf, int k0) {
        cp_async16(&As[buf][ar0*ASTR + ac0],       &A[(size_t)(bm + ar0)*K + k0 + ac0]);
        cp_async16(&As[buf][(ar0+64)*ASTR + ac0],  &A[(size_t)(bm + ar0 + 64)*K + k0 + ac0]);
        cp_async16(&Bs[buf][br0*BSTR + bc0],       &B[(size_t)(k0 + br0)*N + bn + bc0]);
        cp_async16(&Bs[buf][(br0+8)*BSTR + bc0],   &B[(size_t)(k0 + br0 + 8)*N + bn + bc0]);
    };

    load_stage(0, 0);
    cp_commit();

    int nstages = K / 16;
    for (int s = 0; s < nstages; s++) {
        int cur = s & 1;
        if (s + 1 < nstages) { load_stage(cur ^ 1, (s + 1) * 16); cp_commit(); cp_wait<1>(); }
        else                 { cp_wait<0>(); }
        __syncthreads();

        const float* Asb = As[cur];
        const float* Bsb = Bs[cur];
#pragma unroll
        for (int kk = 0; kk < 16; kk += 8) {
            wmma::fragment<wmma::matrix_a, 16, 16, 8, wmma::precision::tf32, wmma::row_major> a[4];
            wmma::fragment<wmma::matrix_b, 16, 16, 8, wmma::precision::tf32, wmma::row_major> b[2];
#pragma unroll
            for (int i = 0; i < 4; i++)
                wmma::load_matrix_sync(a[i], Asb + (wm*64 + i*16)*ASTR + kk, ASTR);
#pragma unroll
            for (int j = 0; j < 2; j++)
                wmma::load_matrix_sync(b[j], Bsb + kk*BSTR + wn*32 + j*16, BSTR);
#pragma unroll
            for (int i = 0; i < 4; i++)
#pragma unroll
                for (int j = 0; j < 2; j++)
                    wmma::mma_sync(acc[i][j], a[i], b[j], acc[i][j]);
        }
        __syncthreads();
    }

    // ---- epilogue: fragment-level fused ops, no smem round trip ----
    int row0 = bm + wm*64;
    int col0 = bn + wn*32;
#pragma unroll
    for (int i = 0; i < 4; i++) {
#pragma unroll
        for (int j = 0; j < 2; j++) {
            float* cp = C + (size_t)(row0 + i*16)*N + col0 + j*16;
            if (EPI == 1) {
                wmma::fragment<wmma::accumulator, 16, 16, 8, float> cf;
                wmma::load_matrix_sync(cf, cp, N, wmma::mem_row_major);
#pragma unroll
                for (int e = 0; e < cf.num_elements; e++) acc[i][j].x[e] += cf.x[e];
            } else if (EPI == 2) {
                const float* rp = R + (size_t)(row0 + i*16)*N + col0 + j*16;
                wmma::fragment<wmma::accumulator, 16, 16, 8, float> rf;
                wmma::load_matrix_sync(rf, rp, N, wmma::mem_row_major);
#pragma unroll
                for (int e = 0; e < rf.num_elements; e++) {
                    float z = acc[i][j].x[e];
                    acc[i][j].x[e] = (z / (1.f + expf(-z))) * rf.x[e];
                }
            }
            wmma::store_matrix_sync(cp, acc[i][j], N, wmma::mem_row_major);
        }
    }
}

// ---------------- Attention (mask-structure-aware flash) ----------------
__global__ void __launch_bounds__(64)
attn_kernel(const float* __restrict__ Q, const float* __restrict__ Kp,
            const float* __restrict__ Vp, float* __restrict__ Op) {
    int b = blockIdx.z, h = blockIdx.y;
    int frame = blockIdx.x / 5, sub = blockIdx.x % 5;
    int q0, nq, k0, kend;
    if (sub < 4) { q0 = frame*TPF + sub*64; nq = 64; k0 = frame*TPF; kend = k0 + 256; }
    else         { q0 = frame*TPF + 256;    nq = 16; k0 = 0;         kend = (frame+1)*TPF; }
    int tq = threadIdx.x;

    __shared__ float Qs[64][68];
    __shared__ float Ks[32][68];
    __shared__ float Vs[32][68];

    size_t bbase = (size_t)b*NTOK*DMODEL + h*HDIM;

    for (int it = 0; it < nq; it++)
        Qs[it][tq] = Q[bbase + (size_t)(q0+it)*DMODEL + tq];
    __syncthreads();

    float mrun = -1e30f, lrun = 0.f;
    float Oa[64];
#pragma unroll
    for (int d = 0; d < 64; d++) Oa[d] = 0.f;

    for (int kt = k0; kt < kend; kt += 32) {
        int kn = kend - kt; if (kn > 32) kn = 32;
#pragma unroll
        for (int r = 0; r < 32; r++) {
            float kv = 0.f, vv = 0.f;
            if (r < kn) {
                kv = Kp[bbase + (size_t)(kt+r)*DMODEL + tq];
                vv = Vp[bbase + (size_t)(kt+r)*DMODEL + tq];
            }
            Ks[r][tq] = kv;
            Vs[r][tq] = vv;
        }
        __syncthreads();

        if (tq < nq) {
            float s[32];
#pragma unroll
            for (int j = 0; j < 32; j++) s[j] = 0.f;
#pragma unroll
            for (int d4 = 0; d4 < 16; d4++) {
                float4 q4 = *(const float4*)&Qs[tq][d4*4];
#pragma unroll
                for (int j = 0; j < 32; j++) {
                    float4 k4 = *(const float4*)&Ks[j][d4*4];
                    s[j] += q4.x*k4.x + q4.y*k4.y + q4.z*k4.z + q4.w*k4.w;
                }
            }
            float mx = -1e30f;
#pragma unroll
            for (int j = 0; j < 32; j++) {
                float sv = 50.f * tanhf(s[j] * (0.125f/50.f));
                s[j] = (kt + j < kend) ? sv : -1e30f;
                mx = fmaxf(mx, s[j]);
            }
            float mnew = fmaxf(mrun, mx);
            float corr = __expf(mrun - mnew);
            lrun *= corr;
#pragma unroll
            for (int d = 0; d < 64; d++) Oa[d] *= corr;
#pragma unroll
            for (int j = 0; j < 32; j++) {
                float p = __expf(s[j] - mnew);
                lrun += p;
#pragma unroll
                for (int d4 = 0; d4 < 16; d4++) {
                    float4 v4 = *(const float4*)&Vs[j][d4*4];
                    Oa[d4*4+0] += p*v4.x; Oa[d4*4+1] += p*v4.y;
                    Oa[d4*4+2] += p*v4.z; Oa[d4*4+3] += p*v4.w;
                }
            }
            mrun = mnew;
        }
        __syncthreads();
    }

    if (tq < nq) {
        float inv = 1.f / lrun;
        float* orow = Op + bbase + (size_t)(q0+tq)*DMODEL;
#pragma unroll
        for (int d = 0; d < 64; d++) orow[d] = Oa[d]*inv;
    }
}

// ---------------- launch ----------------
extern "C" void kernel_launch(void* const* d_in, const int* in_sizes, int n_in,
                              void* d_out, int out_size) {
    const float* x   = (const float*)d_in[0];
    const float* wq  = (const float*)d_in[1];
    const float* wk  = (const float*)d_in[2];
    const float* wv  = (const float*)d_in[3];
    const float* wo  = (const float*)d_in[4];
    const float* qnw = (const float*)d_in[5];
    const float* knw = (const float*)d_in[6];
    const float* n1w = (const float*)d_in[7];
    const float* n2w = (const float*)d_in[8];
    const float* w1  = (const float*)d_in[9];
    const float* w2  = (const float*)d_in[10];
    const float* w3  = (const float*)d_in[11];

    float* xbuf = (float*)d_out;   // residual stream lives in the output buffer

    float *H, *Q, *K, *V, *O, *G;
    cudaGetSymbolAddress((void**)&H, g_H);
    cudaGetSymbolAddress((void**)&Q, g_Q);
    cudaGetSymbolAddress((void**)&K, g_K);
    cudaGetSymbolAddress((void**)&V, g_V);
    cudaGetSymbolAddress((void**)&O, g_O);
    cudaGetSymbolAddress((void**)&G, g_G);

    cudaMemcpyAsync(xbuf, x, sizeof(float)*(size_t)MROWS*DMODEL, cudaMemcpyDeviceToDevice);
    rope_init_kernel<<<256, 64>>>();

    dim3 gD(DMODEL/128, MROWS/128);   // (6, 34)
    dim3 gF(HIDDEN/128, MROWS/128);   // (16, 34)
    dim3 gR(MROWS, 3);
    dim3 gA(20, NHEAD, BATCH);

    for (int l = 0; l < DEPTH; l++) {
        const float* wq_l = wq + (size_t)l*DMODEL*DMODEL;
        const float* wk_l = wk + (size_t)l*DMODEL*DMODEL;
        const float* wv_l = wv + (size_t)l*DMODEL*DMODEL;
        const float* wo_l = wo + (size_t)l*DMODEL*DMODEL;
        const float* w1_l = w1 + (size_t)l*DMODEL*HIDDEN;
        const float* w3_l = w3 + (size_t)l*DMODEL*HIDDEN;
        const float* w2_l = w2 + (size_t)l*HIDDEN*DMODEL;

        // --- attention block ---
        rmsnorm_kernel<<<MROWS, 192>>>(xbuf, n1w + l*DMODEL, H);
        tgemm_kernel<0><<<gD, 256>>>(H, wq_l, Q, Q, MROWS, DMODEL, DMODEL);
        tgemm_kernel<0><<<gD, 256>>>(H, wk_l, K, K, MROWS, DMODEL, DMODEL);
        tgemm_kernel<0><<<gD, 256>>>(H, wv_l, V, V, MROWS, DMODEL, DMODEL);
        rope_qknorm_kernel<<<gR, 128>>>(Q, qnw + l*HDIM);
        rope_qknorm_kernel<<<gR, 128>>>(K, knw + l*HDIM);
        attn_kernel<<<gA, 64>>>(Q, K, V, O);
        tgemm_kernel<1><<<gD, 256>>>(O, wo_l, xbuf, xbuf, MROWS, DMODEL, DMODEL);

        // --- MLP block (SwiGLU) ---
        rmsnorm_kernel<<<MROWS, 192>>>(xbuf, n2w + l*DMODEL, H);
        tgemm_kernel<0><<<gF, 256>>>(H, w3_l, G, G, MROWS, HIDDEN, DMODEL);   // G = h@w3
        tgemm_kernel<2><<<gF, 256>>>(H, w1_l, G, G, MROWS, HIDDEN, DMODEL);   // G = silu(h@w1)*G
        tgemm_kernel<1><<<gD, 256>>>(G, w2_l, xbuf, xbuf, MROWS, DMODEL, HIDDEN);
    }
}